// round 17
// baseline (speedup 1.0000x reference)
#include <cuda_runtime.h>
#include <cuda_fp16.h>
#include <cstdint>

typedef unsigned long long u64;

// ---------------------------------------------------------------------------
// Tensor-core helpers (baseline PTX: ldmatrix sm_75+, mma.sync sm_80+)
// ---------------------------------------------------------------------------
__device__ __forceinline__ uint32_t smem_u32(const void* p) {
    uint32_t a;
    asm("{ .reg .u64 t; cvta.to.shared.u64 t, %1; cvt.u32.u64 %0, t; }" : "=r"(a) : "l"(p));
    return a;
}

#define LDSM_X4(r0, r1, r2, r3, a) \
    asm volatile("ldmatrix.sync.aligned.m8n8.x4.shared.b16 {%0,%1,%2,%3}, [%4];" \
        : "=r"(r0), "=r"(r1), "=r"(r2), "=r"(r3) : "r"(a))
#define LDSM_X4T(r0, r1, r2, r3, a) \
    asm volatile("ldmatrix.sync.aligned.m8n8.x4.trans.shared.b16 {%0,%1,%2,%3}, [%4];" \
        : "=r"(r0), "=r"(r1), "=r"(r2), "=r"(r3) : "r"(a))

// fp16 x fp16 -> fp32 accum
__device__ __forceinline__ void mma16816(float* d, const uint32_t* a,
                                         uint32_t b0, uint32_t b1) {
    asm volatile(
        "mma.sync.aligned.m16n8k16.row.col.f32.f16.f16.f32 "
        "{%0,%1,%2,%3}, {%4,%5,%6,%7}, {%8,%9}, {%0,%1,%2,%3};"
        : "+f"(d[0]), "+f"(d[1]), "+f"(d[2]), "+f"(d[3])
        : "r"(a[0]), "r"(a[1]), "r"(a[2]), "r"(a[3]), "r"(b0), "r"(b1));
}

__device__ __forceinline__ uint32_t hpack(float v0, float v1) {
    return (uint32_t)__half_as_ushort(__float2half_rn(v0))
         | ((uint32_t)__half_as_ushort(__float2half_rn(v1)) << 16);
}

#define STS128(a, r0, r1, r2, r3) \
    asm volatile("st.shared.v4.b32 [%0], {%1,%2,%3,%4};" :: "r"(a), "r"(r0), "r"(r1), "r"(r2), "r"(r3) : "memory")
#define STS64(a, v) \
    asm volatile("st.shared.b64 [%0], %1;" :: "r"(a), "l"(v) : "memory")

// swizzle: flip the 16B slot when bit7 set -> 8 consecutive w pixels (32B
// stride) occupy 8 distinct 16B slots => ldmatrix conflict-free.
#define SWZ(a) ((a) ^ (((a) >> 3) & 0x10))

// ---------------------------------------------------------------------------
// Scratch.  g_y is fp16.
// ---------------------------------------------------------------------------
static __device__ float g_Wm[64 * 64];
static __device__ __half g_y[512u * 16u * 62u * 62u];

// ---------------------------------------------------------------------------
// Kernel 1: tensor-core conv, single-fp16 A and B (y is fp16-quantized
// downstream anyway, so the A lo-term bought nothing).
// grid = 512 images x 4 row-strips (+1 Wm block). 512 thr = 16 warps;
// warp = one output row (16-row strips, 18-row halo). 2 blocks/SM.
// ---------------------------------------------------------------------------
static constexpr int A_SM = 0;          // 18 * 2176 = 39168
static constexpr int B_SM = 39168;      // 9 * 512 = 4608
static constexpr int SM_CONV = 43776;

__global__ __launch_bounds__(512, 2) void conv_tc_kernel(const float* __restrict__ x,
                                                         const float* __restrict__ ker,
                                                         const float* __restrict__ c0p,
                                                         const float* __restrict__ c1p,
                                                         const float* __restrict__ c2p) {
    extern __shared__ __align__(128) char smem[];
    uint32_t sb = smem_u32(smem);
    int tid = threadIdx.x;

    if (blockIdx.x == 2048) {
        // ---- TT-matrix reconstruction (hidden under the conv wave) ----
        float* s0 = reinterpret_cast<float*>(smem);
        float* s1 = s0 + 128;
        float* s2 = s1 + 1024;
        for (int i = tid; i < 128; i += 512) s0[i] = c0p[i];
        for (int i = tid; i < 1024; i += 512) s1[i] = c1p[i];
        for (int i = tid; i < 128; i += 512) s2[i] = c2p[i];
        __syncthreads();
        for (int e = tid; e < 4096; e += 512) {
            int i = e >> 6, j = e & 63;
            int i1 = i >> 4, i2 = (i >> 2) & 3, i3 = i & 3;
            int j1 = j >> 4, j2 = (j >> 2) & 3, j3 = j & 3;
            float s = 0.f;
            #pragma unroll
            for (int r1 = 0; r1 < 8; ++r1) {
                float a = s0[(i1 * 4 + j1) * 8 + r1];
                float t = 0.f;
                #pragma unroll
                for (int r2 = 0; r2 < 8; ++r2)
                    t += s1[((r1 * 4 + i2) * 4 + j2) * 8 + r2] * s2[(r2 * 4 + i3) * 4 + j3];
                s = fmaf(a, t, s);
            }
            g_Wm[e] = s;
        }
        return;
    }

    int bi = blockIdx.x >> 2;
    int strip = blockIdx.x & 3;
    int r0 = strip * 16;

    // zero ONLY the w=64..67 pad slots (18 rows, 2 chunks)
    for (int idx = tid; idx < 144; idx += 512) {
        int chunk = idx & 1;
        int w  = 64 + ((idx >> 1) & 3);
        int rr = idx >> 3;                 // 0..17
        uint32_t raw = (uint32_t)rr * 2176 + w * 32 + chunk * 16;
        STS128(sb + A_SM + SWZ(raw), 0u, 0u, 0u, 0u);
    }

    // B fill: ker flat [co][cin][kh][kw] -> [tap][cin][co] single fp16
    for (int idx = tid; idx < 2304; idx += 512) {
        int co = idx / 144, rem = idx % 144;
        int cin = rem / 9, kk = rem % 9;
        uint32_t raw = (uint32_t)kk * 512 + cin * 32 + co * 2;
        *reinterpret_cast<unsigned short*>(smem + B_SM + SWZ(raw)) =
            __half_as_ushort(__float2half_rn(ker[idx]));
    }

    // A fill: thread = (row, w); pack 16 cin -> 2x STS.128.
    const float* xb = x + (size_t)bi * (16 * 64 * 64);
    for (int idx = tid; idx < 1152; idx += 512) {
        int w  = idx & 63;
        int rr = idx >> 6;                 // 0..17
        int rg = r0 + rr; if (rg > 63) rg = 63;
        const float* src = xb + rg * 64 + w;
        uint32_t ph[8];
        #pragma unroll
        for (int e = 0; e < 8; ++e) {
            float v0 = src[(size_t)(2 * e) * 4096];
            float v1 = src[(size_t)(2 * e + 1) * 4096];
            ph[e] = hpack(v0, v1);
        }
        uint32_t raw0 = (uint32_t)rr * 2176 + w * 32;
        STS128(sb + A_SM + SWZ(raw0), ph[0], ph[1], ph[2], ph[3]);
        STS128(sb + A_SM + SWZ(raw0 + 16), ph[4], ph[5], ph[6], ph[7]);
    }
    __syncthreads();

    int lane = tid & 31;
    int warp = tid >> 5;          // output row within strip (0..15)
    int h = r0 + warp;

    float acc[4][2][4];
    #pragma unroll
    for (int wt = 0; wt < 4; ++wt)
        #pragma unroll
        for (int f = 0; f < 2; ++f)
            #pragma unroll
            for (int e = 0; e < 4; ++e) acc[wt][f][e] = 0.f;

    int arow = lane & 15;
    int khalf = (lane >> 4) * 16;

    #pragma unroll
    for (int kh = 0; kh < 3; ++kh) {
        #pragma unroll
        for (int kw = 0; kw < 3; ++kw) {
            int tap = kh * 3 + kw;
            uint32_t brw = (uint32_t)tap * 512 + arow * 32 + khalf;
            uint32_t bh[4];
            LDSM_X4T(bh[0], bh[1], bh[2], bh[3], sb + B_SM + SWZ(brw));

            uint32_t rbase = (uint32_t)(warp + kh) * 2176;
            #pragma unroll
            for (int wt = 0; wt < 4; ++wt) {
                uint32_t araw = rbase + (wt * 16 + arow + kw) * 32 + khalf;
                uint32_t ah[4];
                LDSM_X4(ah[0], ah[1], ah[2], ah[3], sb + A_SM + SWZ(araw));
                mma16816(acc[wt][0], ah, bh[0], bh[1]);
                mma16816(acc[wt][1], ah, bh[2], bh[3]);
            }
        }
    }

    __syncthreads();  // all A reads done; alias stage buffer onto A region

    // stage: stg[row 16][co 16][w 68] u16 = 34816 B (fits in A region)
    unsigned short* stg = reinterpret_cast<unsigned short*>(smem);
    {
        int wl = lane >> 2;
        int cl = (lane & 3) * 2;
        #pragma unroll
        for (int wt = 0; wt < 4; ++wt)
            #pragma unroll
            for (int f = 0; f < 2; ++f) {
                int w_a = wt * 16 + wl;
                int co = f * 8 + cl;
                unsigned short* p0 = &stg[(warp * 16 + co) * 68 + w_a];
                p0[0]   = __half_as_ushort(__float2half_rn(acc[wt][f][0]));
                p0[68]  = __half_as_ushort(__float2half_rn(acc[wt][f][1]));
                p0[8]   = __half_as_ushort(__float2half_rn(acc[wt][f][2]));
                p0[76]  = __half_as_ushort(__float2half_rn(acc[wt][f][3]));
            }
    }
    __syncthreads();

    // coalesced u16 store to g_y[bi][co][h][w]
    __half* yb = g_y + (size_t)bi * (16 * 62 * 62);
    for (int idx = tid; idx < 16 * 16 * 62; idx += 512) {
        int w = idx % 62;
        int co = (idx / 62) & 15;
        int row = idx / 992;
        int hg = r0 + row;
        if (hg < 62)
            yb[(co * 62 + hg) * 62 + w] = __ushort_as_half(stg[(row * 16 + co) * 68 + w]);
    }
}

// ---------------------------------------------------------------------------
// Kernel 2: mix via mma.sync, single-fp16 A/B, warp tile m32 x n64.
// A stored [i 64][p 272 halves] (pitch 544B): fill is fully coalesced
// (uint2 = 4 consecutive p per thread), fragments via ldmatrix.x4.trans
// (pitch 544 -> slot = 2r + c covers all 32 banks, conflict-free).
// ---------------------------------------------------------------------------
static constexpr int APITCH = 544;
static constexpr int BPITCH = 144;
static constexpr int SM_A    = 0;          // 64*544 = 34816
static constexpr int SM_B    = 34816;      // 64*144 = 9216
static constexpr int SM_BIAS = 44032;
static constexpr int SM_MIX  = 44288;

__global__ __launch_bounds__(256) void mix_mma_kernel(const float* __restrict__ bias,
                                                      float* __restrict__ out) {
    extern __shared__ __align__(16) char smem[];
    uint32_t sb = smem_u32(smem);
    int tid = threadIdx.x;
    int lane = tid & 31;
    int warp = tid >> 5;
    int co = blockIdx.y;
    int b  = blockIdx.z;
    int p_base = blockIdx.x * 256;

    // ---- A = y [i][p] fp16, coalesced: thread = (i, 4-p chunk) ----
    {
        const __half* yco = g_y + ((size_t)(b * 64) * 16 + co) * 3844;
        #pragma unroll
        for (int it = 0; it < 16; ++it) {
            int u = it * 256 + tid;
            int i = u >> 6;
            int pq = u & 63;
            int pg = p_base + pq * 4;
            const __half* src = yco + (size_t)i * (16 * 3844) + pg;
            uint2 v = make_uint2(0u, 0u);
            if (pg + 3 < 3844) {
                v = *reinterpret_cast<const uint2*>(src);
            } else if (pg < 3844) {
                unsigned short t[4] = {0, 0, 0, 0};
                #pragma unroll
                for (int e = 0; e < 4; ++e)
                    if (pg + e < 3844) t[e] = __half_as_ushort(src[e]);
                v.x = (uint32_t)t[0] | ((uint32_t)t[1] << 16);
                v.y = (uint32_t)t[2] | ((uint32_t)t[3] << 16);
            }
            u64 vv = (u64)v.x | ((u64)v.y << 32);
            STS64(sb + SM_A + i * APITCH + pq * 8, vv);
        }
    }

    // ---- B = Wm single fp16 [i][j], row-major, pitch 144B ----
    if (tid < 128) {
        int i = tid & 63;
        int jh = tid >> 6;
        int j0 = jh * 32;
        const float4* src = reinterpret_cast<const float4*>(&g_Wm[i * 64 + j0]);
        uint32_t base = sb + SM_B + i * BPITCH + j0 * 2;
        #pragma unroll
        for (int q = 0; q < 4; ++q) {
            float4 v0 = src[2 * q];
            float4 v1 = src[2 * q + 1];
            STS128(base + q * 16, hpack(v0.x, v0.y), hpack(v0.z, v0.w),
                   hpack(v1.x, v1.y), hpack(v1.z, v1.w));
        }
    }
    if (tid < 64)
        *reinterpret_cast<float*>(smem + SM_BIAS + tid * 4) = bias[tid];
    __syncthreads();

    float acc[2][8][4];
    #pragma unroll
    for (int mt = 0; mt < 2; ++mt)
        #pragma unroll
        for (int nt = 0; nt < 8; ++nt)
            #pragma unroll
            for (int e = 0; e < 4; ++e) acc[mt][nt][e] = 0.f;

    // trans-A fragment base: row = (lane&7) + ((lane>>4)<<3), col-half = (lane>>3)&1
    uint32_t a_base = sb + SM_A
                    + (uint32_t)((lane & 7) + ((lane >> 4) << 3)) * APITCH
                    + ((lane >> 3) & 1) * 16
                    + warp * 64;
    uint32_t b_kr = (lane & 15);
    uint32_t b_jc = (lane >> 4) * 8;

    #pragma unroll
    for (int k = 0; k < 4; ++k) {
        uint32_t a0[4], a1[4];
        LDSM_X4T(a0[0], a0[1], a0[2], a0[3], a_base + k * (16 * APITCH));
        LDSM_X4T(a1[0], a1[1], a1[2], a1[3], a_base + k * (16 * APITCH) + 32);

        #pragma unroll
        for (int jp = 0; jp < 4; ++jp) {
            uint32_t baddr = sb + SM_B + (k * 16 + b_kr) * BPITCH + (jp * 16 + b_jc) * 2;
            uint32_t bh[4];
            LDSM_X4T(bh[0], bh[1], bh[2], bh[3], baddr);
            mma16816(acc[0][2 * jp],     a0, bh[0], bh[1]);
            mma16816(acc[0][2 * jp + 1], a0, bh[2], bh[3]);
            mma16816(acc[1][2 * jp],     a1, bh[0], bh[1]);
            mma16816(acc[1][2 * jp + 1], a1, bh[2], bh[3]);
        }
    }

    size_t rowbase = (size_t)(b * 16 + co) * 3844;
    int jsub = (lane & 3) * 2;

    #pragma unroll
    for (int mt = 0; mt < 2; ++mt) {
        int row0 = warp * 32 + mt * 16 + (lane >> 2);
        int pm0 = p_base + row0;
        int pm1 = pm0 + 8;
        #pragma unroll
        for (int nt = 0; nt < 8; ++nt) {
            int j = nt * 8 + jsub;
            float2 bv = *reinterpret_cast<const float2*>(smem + SM_BIAS + j * 4);
            if (pm0 < 3844)
                *reinterpret_cast<float2*>(&out[(rowbase + pm0) * 64 + j]) =
                    make_float2(acc[mt][nt][0] + bv.x, acc[mt][nt][1] + bv.y);
            if (pm1 < 3844)
                *reinterpret_cast<float2*>(&out[(rowbase + pm1) * 64 + j]) =
                    make_float2(acc[mt][nt][2] + bv.x, acc[mt][nt][3] + bv.y);
        }
    }
}

// ---------------------------------------------------------------------------
extern "C" void kernel_launch(void* const* d_in, const int* in_sizes, int n_in,
                              void* d_out, int out_size) {
    const float* x    = (const float*)d_in[0];
    const float* ker  = (const float*)d_in[1];
    const float* c0   = (const float*)d_in[2];
    const float* c1   = (const float*)d_in[3];
    const float* c2   = (const float*)d_in[4];
    const float* bias = (const float*)d_in[5];
    float* out = (float*)d_out;

    cudaFuncSetAttribute(conv_tc_kernel,
                         cudaFuncAttributeMaxDynamicSharedMemorySize, SM_CONV);
    cudaFuncSetAttribute(mix_mma_kernel,
                         cudaFuncAttributeMaxDynamicSharedMemorySize, SM_MIX);

    conv_tc_kernel<<<2049, 512, SM_CONV>>>(x, ker, c0, c1, c2);
    mix_mma_kernel<<<dim3(16, 16, 8), 256, SM_MIX>>>(bias, out);
}